// round 10
// baseline (speedup 1.0000x reference)
#include <cuda_runtime.h>
#include <cstdint>

// Problem constants
#define BATCH 32
#define NNODE 4096
#define INDIM 64
#define HDIM  128

// ---------------- fused aggregation+projection kernel config ----------------
#define FBM 256
#define FBN 128
#define FBK 32
#define FSA_STRIDE 36     // 32+4: A-frag LDS banks (4g+t)%32 distinct
#define FSB_STRIDE 136    // 128+8: B-frag LDS banks (8t+g)%32 distinct
#define AGG_STRIDE 132    // aggS A-frag banks (4g+t)%32 distinct
#define W_STRIDE  136

// smem layout (floats):
//  [0 .. 18432)              pipeline As (2 stages x 256x36)
//  [18432 .. 27136)          pipeline Bs (2 stages x 32x136)
//  [0 .. 33792)              aggS (256x132)  -- REUSES pipeline region post-mainloop
//  [33792 .. 51200)          W    (128x136)
#define PIPE_AS_OFF 0
#define PIPE_BS_OFF 18432
#define AGGS_OFF    0
#define WSM_OFF     33792
#define FUSED_SMEM_FLOATS 51200
#define FUSED_SMEM_BYTES  (FUSED_SMEM_FLOATS * 4)   // 200 KB

// ---------------- fc kernel config (proven R4 config) ----------------
#define BM 128
#define BN 128
#define BK 16
#define SA_STRIDE 20
#define SB_STRIDE 136

// ---------------------------------------------------------------------------
// SINGLE device global, 128 MB + 160 KB (footprint that has passed):
//   [0,      BNH)  : hr (tf32-rounded shadow of h)
//   [BNH,  2*BNH)  : t  (tf32-rounded gcn1 output)
//   [2*BNH, +40960): rounded W_fc | W1 | W2
// fp32 Euler state h lives in d_out.
// ---------------------------------------------------------------------------
#define BNH ((size_t)BATCH * NNODE * HDIM)
#define W_OFF (2 * BNH)
__device__ __align__(256) float g_scratch[2 * BNH + 40960];

__device__ __forceinline__ uint32_t cvt_tf32(float x) {
    uint32_t r;
    asm("cvt.rna.tf32.f32 %0, %1;" : "=r"(r) : "f"(x));
    return r;
}
__device__ __forceinline__ float round_tf32(float x) {
    return __uint_as_float(cvt_tf32(x));
}

__device__ __forceinline__ void mma_tf32(float c[4],
                                         uint32_t a0, uint32_t a1, uint32_t a2, uint32_t a3,
                                         uint32_t b0, uint32_t b1) {
    asm volatile(
        "mma.sync.aligned.m16n8k8.row.col.f32.tf32.tf32.f32 "
        "{%0,%1,%2,%3}, {%4,%5,%6,%7}, {%8,%9}, {%0,%1,%2,%3};\n"
        : "+f"(c[0]), "+f"(c[1]), "+f"(c[2]), "+f"(c[3])
        : "r"(a0), "r"(a1), "r"(a2), "r"(a3), "r"(b0), "r"(b1));
}

__device__ __forceinline__ void cp_async16(void* smem, const void* gmem) {
    uint32_t s = (uint32_t)__cvta_generic_to_shared(smem);
    asm volatile("cp.async.cg.shared.global [%0], [%1], 16;\n" :: "r"(s), "l"(gmem));
}
#define CP_COMMIT() asm volatile("cp.async.commit_group;\n" ::: "memory")
#define CP_WAIT0()  asm volatile("cp.async.wait_group 0;\n" ::: "memory")

// Element-wise tf32 rounding pre-pass for the small weight matrices.
__global__ void round_copy_kernel(const float* __restrict__ in, float* __restrict__ out, int n4) {
    int i = blockIdx.x * blockDim.x + threadIdx.x;
    if (i < n4) {
        float4 v = reinterpret_cast<const float4*>(in)[i];
        v.x = round_tf32(v.x); v.y = round_tf32(v.y);
        v.z = round_tf32(v.z); v.w = round_tf32(v.w);
        reinterpret_cast<float4*>(out)[i] = v;
    }
}

// ===========================================================================
// Fused GCN layer kernel. Per CTA (256 nodes x 128 hidden):
//   agg = adj[rows,:] @ Bsrc          (K = 4096, tf32 mma, A rounded in-loop)
//   acc2 = round(agg) @ Wr            (K = 128, on-chip via smem staging)
//   EULER == 0:  Cdst = round(relu(acc2 + bias))                      (-> t)
//   EULER == 1:  hn = h + 0.25*relu(acc2 + bias); h = hn; Cdst = round(hn)
// Bsrc/Cdst/h are batched over blockIdx.z with stride NNODE*HDIM.
// ===========================================================================
template <int EULER>
__global__ __launch_bounds__(512, 1)
void gcn_fused_kernel(const float* __restrict__ adj, const float* __restrict__ Bsrc,
                      const float* __restrict__ Wr, const float* __restrict__ bias,
                      float* __restrict__ Cdst, float* __restrict__ hbuf)
{
    extern __shared__ __align__(16) float smem[];
    float* As   = smem + PIPE_AS_OFF;
    float* Bs   = smem + PIPE_BS_OFF;
    float* aggS = smem + AGGS_OFF;
    float* Wsm  = smem + WSM_OFF;

    const long long sNH = (long long)NNODE * HDIM;
    const int bz = blockIdx.z;
    const float* Bb = Bsrc + (long long)bz * sNH;
    float* Cb = Cdst + (long long)bz * sNH;
    float* hb = hbuf ? (hbuf + (long long)bz * sNH) : nullptr;

    const int bm = blockIdx.y * FBM;

    const int tid  = threadIdx.x;
    const int lane = tid & 31;
    const int warp = tid >> 5;
    const int wm = (warp & 7) * 32;   // 8 warps along M (8*32 = 256)
    const int wn = (warp >> 3) * 64;  // 2 warps along N (2*64 = 128)
    const int g = lane >> 2;
    const int t = lane & 3;

    // Preload W (128x128 rounded) into its own smem region; joins group 0.
    {
        const int n4 = (HDIM * HDIM) / 4;   // 4096 float4
        for (int i = tid; i < n4; i += 512) {
            int r = i >> 5;
            int c = (i & 31) << 2;
            cp_async16(&Wsm[r * W_STRIDE + c], Wr + r * HDIM + c);
        }
    }

    float acc[2][8][4];
    #pragma unroll
    for (int mt = 0; mt < 2; mt++)
        #pragma unroll
        for (int nt = 0; nt < 8; nt++)
            #pragma unroll
            for (int i = 0; i < 4; i++)
                acc[mt][nt][i] = 0.0f;

    auto load_stage = [&](int stage, int kt) {
        float* as = As + stage * (FBM * FSA_STRIDE);
        const float* Ag = adj + (long long)bm * NNODE + (long long)kt * FBK;
        #pragma unroll
        for (int i = 0; i < 4; i++) {            // 256x32 floats = 2048 float4
            int idx = tid + i * 512;
            int r = idx >> 3;
            int c = (idx & 7) << 2;
            cp_async16(&as[r * FSA_STRIDE + c], Ag + (long long)r * NNODE + c);
        }
        float* bs = Bs + stage * (FBK * FSB_STRIDE);
        const float* Bg = Bb + (long long)(kt * FBK) * HDIM;
        #pragma unroll
        for (int i = 0; i < 2; i++) {            // 32x128 floats = 1024 float4
            int idx = tid + i * 512;
            int r = idx >> 5;
            int c = (idx & 31) << 2;
            cp_async16(&bs[r * FSB_STRIDE + c], Bg + (long long)r * HDIM + c);
        }
    };

    auto compute_stage = [&](int stage) {
        const float* as = As + stage * (FBM * FSA_STRIDE);
        const float* bs = Bs + stage * (FBK * FSB_STRIDE);
        #pragma unroll
        for (int ks = 0; ks < FBK; ks += 8) {
            uint32_t af[2][4];
            #pragma unroll
            for (int mt = 0; mt < 2; mt++) {
                const int rb = wm + mt * 16;
                af[mt][0] = cvt_tf32(as[(rb + g)     * FSA_STRIDE + ks + t]);
                af[mt][1] = cvt_tf32(as[(rb + g + 8) * FSA_STRIDE + ks + t]);
                af[mt][2] = cvt_tf32(as[(rb + g)     * FSA_STRIDE + ks + t + 4]);
                af[mt][3] = cvt_tf32(as[(rb + g + 8) * FSA_STRIDE + ks + t + 4]);
            }
            uint32_t bf[8][2];
            #pragma unroll
            for (int nt = 0; nt < 8; nt++) {
                const int nb = wn + nt * 8 + g;
                bf[nt][0] = __float_as_uint(bs[(ks + t)     * FSB_STRIDE + nb]);
                bf[nt][1] = __float_as_uint(bs[(ks + t + 4) * FSB_STRIDE + nb]);
            }
            #pragma unroll
            for (int mt = 0; mt < 2; mt++)
                #pragma unroll
                for (int nt = 0; nt < 8; nt++)
                    mma_tf32(acc[mt][nt], af[mt][0], af[mt][1], af[mt][2], af[mt][3],
                             bf[nt][0], bf[nt][1]);
        }
    };

    const int nk = NNODE / FBK;   // 128
    load_stage(0, 0);
    CP_COMMIT();
    CP_WAIT0();
    __syncthreads();

    for (int kt = 0; kt < nk; kt++) {
        const int s = kt & 1;
        if (kt + 1 < nk) {
            load_stage(s ^ 1, kt + 1);
            CP_COMMIT();
        }
        compute_stage(s);
        if (kt + 1 < nk) {
            CP_WAIT0();
            __syncthreads();
        }
    }

    // ---- stage rounded agg into smem (overwrites dead pipeline buffers) ----
    __syncthreads();
    #pragma unroll
    for (int mt = 0; mt < 2; mt++) {
        #pragma unroll
        for (int nt = 0; nt < 8; nt++) {
            #pragma unroll
            for (int half = 0; half < 2; half++) {
                const int row = wm + mt * 16 + g + half * 8;
                const int col = wn + nt * 8 + t * 2;
                float2 v = { round_tf32(acc[mt][nt][half * 2 + 0]),
                             round_tf32(acc[mt][nt][half * 2 + 1]) };
                *reinterpret_cast<float2*>(&aggS[row * AGG_STRIDE + col]) = v;
            }
        }
    }
    __syncthreads();

    // ---- on-chip projection: acc2 = aggS @ Wsm  (K = 128) ----
    #pragma unroll
    for (int mt = 0; mt < 2; mt++)
        #pragma unroll
        for (int nt = 0; nt < 8; nt++)
            #pragma unroll
            for (int i = 0; i < 4; i++)
                acc[mt][nt][i] = 0.0f;

    #pragma unroll
    for (int ks = 0; ks < HDIM; ks += 8) {
        uint32_t af[2][4];
        #pragma unroll
        for (int mt = 0; mt < 2; mt++) {
            const int rb = wm + mt * 16;
            af[mt][0] = __float_as_uint(aggS[(rb + g)     * AGG_STRIDE + ks + t]);
            af[mt][1] = __float_as_uint(aggS[(rb + g + 8) * AGG_STRIDE + ks + t]);
            af[mt][2] = __float_as_uint(aggS[(rb + g)     * AGG_STRIDE + ks + t + 4]);
            af[mt][3] = __float_as_uint(aggS[(rb + g + 8) * AGG_STRIDE + ks + t + 4]);
        }
        uint32_t bf[8][2];
        #pragma unroll
        for (int nt = 0; nt < 8; nt++) {
            const int nb = wn + nt * 8 + g;
            bf[nt][0] = __float_as_uint(Wsm[(ks + t)     * W_STRIDE + nb]);
            bf[nt][1] = __float_as_uint(Wsm[(ks + t + 4) * W_STRIDE + nb]);
        }
        #pragma unroll
        for (int mt = 0; mt < 2; mt++)
            #pragma unroll
            for (int nt = 0; nt < 8; nt++)
                mma_tf32(acc[mt][nt], af[mt][0], af[mt][1], af[mt][2], af[mt][3],
                         bf[nt][0], bf[nt][1]);
    }

    // ---- final epilogue ----
    #pragma unroll
    for (int mt = 0; mt < 2; mt++) {
        #pragma unroll
        for (int nt = 0; nt < 8; nt++) {
            #pragma unroll
            for (int half = 0; half < 2; half++) {
                const int row = bm + wm + mt * 16 + g + half * 8;
                const int col = wn + nt * 8 + t * 2;
                float v0 = acc[mt][nt][half * 2 + 0] + bias[col];
                float v1 = acc[mt][nt][half * 2 + 1] + bias[col + 1];
                const long long off = (long long)row * HDIM + col;
                if (EULER == 0) {
                    float2 o = { round_tf32(fmaxf(v0, 0.0f)),
                                 round_tf32(fmaxf(v1, 0.0f)) };
                    *reinterpret_cast<float2*>(&Cb[off]) = o;
                } else {
                    float2 hin = *reinterpret_cast<const float2*>(&hb[off]);
                    float2 hn = { hin.x + 0.25f * fmaxf(v0, 0.0f),
                                  hin.y + 0.25f * fmaxf(v1, 0.0f) };
                    *reinterpret_cast<float2*>(&hb[off]) = hn;
                    float2 r2 = { round_tf32(hn.x), round_tf32(hn.y) };
                    *reinterpret_cast<float2*>(&Cb[off]) = r2;
                }
            }
        }
    }
}

// ===========================================================================
// fc kernel (proven R4/R6 config): h = x @ W_fc + b_fc, dual write h + hr.
// A (= x) rounded in-loop; B pre-rounded.
// ===========================================================================
__global__ __launch_bounds__(256, 2)
void fc_kernel(const float* __restrict__ A, const float* __restrict__ Bm,
               float* __restrict__ C, float* __restrict__ Cr,
               const float* __restrict__ bias)
{
    __shared__ __align__(16) float As[2][BM * SA_STRIDE];
    __shared__ __align__(16) float Bs[2][BK * SB_STRIDE];

    const int K = INDIM, N = HDIM;
    const int bm = blockIdx.y * BM;

    const int tid  = threadIdx.x;
    const int lane = tid & 31;
    const int warp = tid >> 5;
    const int wm = (warp & 3) * 32;
    const int wn = (warp >> 2) * 64;
    const int g = lane >> 2;
    const int t = lane & 3;

    float acc[2][8][4];
    #pragma unroll
    for (int mt = 0; mt < 2; mt++)
        #pragma unroll
        for (int nt = 0; nt < 8; nt++)
            #pragma unroll
            for (int i = 0; i < 4; i++)
                acc[mt][nt][i] = 0.0f;

    auto load_stage = [&](int stage, int kt) {
        const float* Ag = A + (long long)bm * K + (long long)kt * BK;
        #pragma unroll
        for (int i = 0; i < 2; i++) {
            int idx = tid + i * 256;
            int r = idx >> 2;
            int c = (idx & 3) << 2;
            cp_async16(&As[stage][r * SA_STRIDE + c], Ag + (long long)r * K + c);
        }
        const float* Bg = Bm + (long long)(kt * BK) * N;
        #pragma unroll
        for (int i = 0; i < 2; i++) {
            int idx = tid + i * 256;
            int r = idx >> 5;
            int c = (idx & 31) << 2;
            cp_async16(&Bs[stage][r * SB_STRIDE + c], Bg + (long long)r * N + c);
        }
    };

    auto compute_stage = [&](int stage) {
        #pragma unroll
        for (int ks = 0; ks < BK; ks += 8) {
            uint32_t af[2][4];
            #pragma unroll
            for (int mt = 0; mt < 2; mt++) {
                const int rb = wm + mt * 16;
                af[mt][0] = cvt_tf32(As[stage][(rb + g)     * SA_STRIDE + ks + t]);
                af[mt][1] = cvt_tf32(As[stage][(rb + g + 8) * SA_STRIDE + ks + t]);
                af[mt][2] = cvt_tf32(As[stage][(rb + g)     * SA_STRIDE + ks + t + 4]);
                af[mt][3] = cvt_tf32(As[stage][(rb + g + 8) * SA_STRIDE + ks + t + 4]);
            }
            uint32_t bf[8][2];
            #pragma unroll
            for (int nt = 0; nt < 8; nt++) {
                const int nb = wn + nt * 8 + g;
                bf[nt][0] = __float_as_uint(Bs[stage][(ks + t)     * SB_STRIDE + nb]);
                bf[nt][1] = __float_as_uint(Bs[stage][(ks + t + 4) * SB_STRIDE + nb]);
            }
            #pragma unroll
            for (int mt = 0; mt < 2; mt++)
                #pragma unroll
                for (int nt = 0; nt < 8; nt++)
                    mma_tf32(acc[mt][nt], af[mt][0], af[mt][1], af[mt][2], af[mt][3],
                             bf[nt][0], bf[nt][1]);
        }
    };

    const int nk = K / BK;
    load_stage(0, 0);
    CP_COMMIT();
    CP_WAIT0();
    __syncthreads();

    for (int kt = 0; kt < nk; kt++) {
        const int s = kt & 1;
        if (kt + 1 < nk) {
            load_stage(s ^ 1, kt + 1);
            CP_COMMIT();
        }
        compute_stage(s);
        if (kt + 1 < nk) {
            CP_WAIT0();
            __syncthreads();
        }
    }

    #pragma unroll
    for (int mt = 0; mt < 2; mt++) {
        #pragma unroll
        for (int nt = 0; nt < 8; nt++) {
            #pragma unroll
            for (int half = 0; half < 2; half++) {
                const int row = bm + wm + mt * 16 + g + half * 8;
                const int col = wn + nt * 8 + t * 2;
                float v0 = acc[mt][nt][half * 2 + 0] + bias[col];
                float v1 = acc[mt][nt][half * 2 + 1] + bias[col + 1];
                const long long off = (long long)row * N + col;
                float2 o = { v0, v1 };
                *reinterpret_cast<float2*>(&C[off]) = o;
                float2 r2 = { round_tf32(v0), round_tf32(v1) };
                *reinterpret_cast<float2*>(&Cr[off]) = r2;
            }
        }
    }
}

extern "C" void kernel_launch(void* const* d_in, const int* in_sizes, int n_in,
                              void* d_out, int out_size)
{
    const float* x    = (const float*)d_in[0];
    const float* adj  = (const float*)d_in[1];
    const float* W_fc = (const float*)d_in[2];
    const float* b_fc = (const float*)d_in[3];
    const float* W1   = (const float*)d_in[4];
    const float* b1   = (const float*)d_in[5];
    const float* W2   = (const float*)d_in[6];
    const float* b2   = (const float*)d_in[7];
    float* out = (float*)d_out;

    float* base;
    cudaGetSymbolAddress((void**)&base, g_scratch);
    float* hr    = base;                     // rounded shadow of h
    float* tbuf  = base + BNH;               // rounded gcn1 output
    float* wfc_r = base + W_OFF;
    float* w1_r  = wfc_r + INDIM * HDIM;
    float* w2_r  = w1_r  + HDIM * HDIM;
    float* h = out;                          // fp32 Euler state

    cudaFuncSetAttribute(gcn_fused_kernel<0>,
                         cudaFuncAttributeMaxDynamicSharedMemorySize, FUSED_SMEM_BYTES);
    cudaFuncSetAttribute(gcn_fused_kernel<1>,
                         cudaFuncAttributeMaxDynamicSharedMemorySize, FUSED_SMEM_BYTES);

    // Pre-round the weight matrices.
    {
        const int thr = 256;
        int n4 = (INDIM * HDIM) / 4;
        round_copy_kernel<<<(n4 + thr - 1) / thr, thr>>>(W_fc, wfc_r, n4);
        n4 = (HDIM * HDIM) / 4;
        round_copy_kernel<<<(n4 + thr - 1) / thr, thr>>>(W1, w1_r, n4);
        round_copy_kernel<<<(n4 + thr - 1) / thr, thr>>>(W2, w2_r, n4);
    }

    // h = x @ W_fc + b_fc  (fp32 h + rounded shadow hr)
    fc_kernel<<<dim3(1, (BATCH * NNODE) / BM, 1), 256>>>(x, wfc_r, h, hr, b_fc);

    const dim3 fgrid(1, NNODE / FBM, BATCH);
    for (int step = 0; step < 4; step++) {
        // t = round(relu((adj @ hr) @ W1 + b1))
        gcn_fused_kernel<0><<<fgrid, 512, FUSED_SMEM_BYTES>>>(
            adj, hr, w1_r, b1, tbuf, nullptr);
        // h += 0.25*relu((adj @ t) @ W2 + b2);  hr = round(h)
        gcn_fused_kernel<1><<<fgrid, 512, FUSED_SMEM_BYTES>>>(
            adj, tbuf, w2_r, b2, hr, h);
    }
}

// round 11
// speedup vs baseline: 1.3378x; 1.3378x over previous
#include <cuda_runtime.h>
#include <cstdint>

// Problem constants
#define BATCH 32
#define NNODE 4096
#define INDIM 64
#define HDIM  128

// ---------------- generic (fc/projection) kernel config: proven R7 ----------
#define BM 128
#define BN 128
#define BK 16
#define SA_STRIDE 20
#define SB_STRIDE 136

// ---------------- aggregation kernel config: 3-stage, BK=32 -----------------
#define TBM 128
#define TBN 128
#define TBK 32
#define TSA 36            // 32+4: A-frag banks (4g+t)%32 distinct
#define TSB 136           // 128+8: B-frag banks (8t+g)%32 distinct
#define STAGE_A (TBM * TSA)          // 4608 floats
#define STAGE_B (TBK * TSB)          // 4352 floats
#define NSTAGE 3
#define AGG_SMEM_FLOATS (NSTAGE * (STAGE_A + STAGE_B))   // 26880
#define AGG_SMEM_BYTES  (AGG_SMEM_FLOATS * 4)            // 107520 B -> 2 CTA/SM

// ---------------------------------------------------------------------------
// SINGLE device global, 128 MB + 160 KB (proven footprint):
//   [0,      BNH)  : agg   (tf32-rounded aggregation output)
//   [BNH,  2*BNH)  : t/hr  (dual-purpose; liveness disjoint)
//   [2*BNH, +40960): rounded W_fc | W1 | W2
// fp32 Euler state h lives in d_out.
// ---------------------------------------------------------------------------
#define BNH ((size_t)BATCH * NNODE * HDIM)
#define W_OFF (2 * BNH)
__device__ __align__(256) float g_scratch[2 * BNH + 40960];

__device__ __forceinline__ uint32_t cvt_tf32(float x) {
    uint32_t r;
    asm("cvt.rna.tf32.f32 %0, %1;" : "=r"(r) : "f"(x));
    return r;
}
__device__ __forceinline__ float round_tf32(float x) {
    return __uint_as_float(cvt_tf32(x));
}

__device__ __forceinline__ void mma_tf32(float c[4],
                                         uint32_t a0, uint32_t a1, uint32_t a2, uint32_t a3,
                                         uint32_t b0, uint32_t b1) {
    asm volatile(
        "mma.sync.aligned.m16n8k8.row.col.f32.tf32.tf32.f32 "
        "{%0,%1,%2,%3}, {%4,%5,%6,%7}, {%8,%9}, {%0,%1,%2,%3};\n"
        : "+f"(c[0]), "+f"(c[1]), "+f"(c[2]), "+f"(c[3])
        : "r"(a0), "r"(a1), "r"(a2), "r"(a3), "r"(b0), "r"(b1));
}

__device__ __forceinline__ void cp_async16(void* smem, const void* gmem) {
    uint32_t s = (uint32_t)__cvta_generic_to_shared(smem);
    asm volatile("cp.async.cg.shared.global [%0], [%1], 16;\n" :: "r"(s), "l"(gmem));
}
#define CP_COMMIT() asm volatile("cp.async.commit_group;\n" ::: "memory")
#define CP_WAIT0()  asm volatile("cp.async.wait_group 0;\n" ::: "memory")
#define CP_WAIT1()  asm volatile("cp.async.wait_group 1;\n" ::: "memory")

// Element-wise tf32 rounding pre-pass for the small weight matrices.
__global__ void round_copy_kernel(const float* __restrict__ in, float* __restrict__ out, int n4) {
    int i = blockIdx.x * blockDim.x + threadIdx.x;
    if (i < n4) {
        float4 v = reinterpret_cast<const float4*>(in)[i];
        v.x = round_tf32(v.x); v.y = round_tf32(v.y);
        v.z = round_tf32(v.z); v.w = round_tf32(v.w);
        reinterpret_cast<float4*>(out)[i] = v;
    }
}

// ===========================================================================
// Aggregation GEMM: C[b] = round(adj @ B[b]),  M=N? no: M=4096, N=128, K=4096.
// 3-stage cp.async pipeline, BK=32, 2 CTAs/SM. adj rounded in-loop (rna);
// B (hr or t) pre-rounded.
// ===========================================================================
__global__ __launch_bounds__(256, 2)
void agg_kernel(const float* __restrict__ adj, const float* __restrict__ Bsrc,
                float* __restrict__ Cdst)
{
    extern __shared__ __align__(16) float dsm[];
    float* As = dsm;                       // NSTAGE x (128 x 36)
    float* Bs = dsm + NSTAGE * STAGE_A;    // NSTAGE x (32 x 136)

    const long long sNH = (long long)NNODE * HDIM;
    const int bz = blockIdx.z;
    const float* Bb = Bsrc + (long long)bz * sNH;
    float* Cb = Cdst + (long long)bz * sNH;

    const int bm = blockIdx.y * TBM;

    const int tid  = threadIdx.x;
    const int lane = tid & 31;
    const int warp = tid >> 5;
    const int wm = (warp & 3) * 32;   // 4 warps along M
    const int wn = (warp >> 2) * 64;  // 2 warps along N
    const int g = lane >> 2;
    const int t = lane & 3;

    float acc[2][8][4];
    #pragma unroll
    for (int mt = 0; mt < 2; mt++)
        #pragma unroll
        for (int nt = 0; nt < 8; nt++)
            #pragma unroll
            for (int i = 0; i < 4; i++)
                acc[mt][nt][i] = 0.0f;

    auto load_stage = [&](int stage, int kt) {
        float* as = As + stage * STAGE_A;
        const float* Ag = adj + (long long)bm * NNODE + (long long)kt * TBK;
        #pragma unroll
        for (int i = 0; i < 4; i++) {          // 128x32 floats = 1024 float4
            int idx = tid + i * 256;
            int r = idx >> 3;
            int c = (idx & 7) << 2;
            cp_async16(&as[r * TSA + c], Ag + (long long)r * NNODE + c);
        }
        float* bs = Bs + stage * STAGE_B;
        const float* Bg = Bb + (long long)(kt * TBK) * HDIM;
        #pragma unroll
        for (int i = 0; i < 4; i++) {          // 32x128 floats = 1024 float4
            int idx = tid + i * 256;
            int r = idx >> 5;
            int c = (idx & 31) << 2;
            cp_async16(&bs[r * TSB + c], Bg + (long long)r * HDIM + c);
        }
    };

    auto compute_stage = [&](int stage) {
        const float* as = As + stage * STAGE_A;
        const float* bs = Bs + stage * STAGE_B;
        #pragma unroll
        for (int ks = 0; ks < TBK; ks += 8) {
            uint32_t af[2][4];
            #pragma unroll
            for (int mt = 0; mt < 2; mt++) {
                const int rb = wm + mt * 16;
                af[mt][0] = cvt_tf32(as[(rb + g)     * TSA + ks + t]);
                af[mt][1] = cvt_tf32(as[(rb + g + 8) * TSA + ks + t]);
                af[mt][2] = cvt_tf32(as[(rb + g)     * TSA + ks + t + 4]);
                af[mt][3] = cvt_tf32(as[(rb + g + 8) * TSA + ks + t + 4]);
            }
            uint32_t bf[8][2];
            #pragma unroll
            for (int nt = 0; nt < 8; nt++) {
                const int nb = wn + nt * 8 + g;
                bf[nt][0] = __float_as_uint(bs[(ks + t)     * TSB + nb]);
                bf[nt][1] = __float_as_uint(bs[(ks + t + 4) * TSB + nb]);
            }
            #pragma unroll
            for (int mt = 0; mt < 2; mt++)
                #pragma unroll
                for (int nt = 0; nt < 8; nt++)
                    mma_tf32(acc[mt][nt], af[mt][0], af[mt][1], af[mt][2], af[mt][3],
                             bf[nt][0], bf[nt][1]);
        }
    };

    const int nk = NNODE / TBK;   // 128
    // Prologue: two stages in flight.
    load_stage(0, 0); CP_COMMIT();
    load_stage(1, 1); CP_COMMIT();
    CP_WAIT1();            // stage 0 complete (stage 1 may still be in flight)
    __syncthreads();

    for (int kt = 0; kt < nk; kt++) {
        compute_stage(kt % NSTAGE);
        if (kt + 1 < nk) {
            if (kt + 2 < nk) {
                load_stage((kt + 2) % NSTAGE, kt + 2);
                CP_COMMIT();
                CP_WAIT1();   // ensures stage kt+1 is complete
            } else {
                CP_WAIT0();   // last iteration: drain everything
            }
            __syncthreads();
        }
    }

    // Epilogue: rounded store.
    #pragma unroll
    for (int mt = 0; mt < 2; mt++) {
        #pragma unroll
        for (int nt = 0; nt < 8; nt++) {
            #pragma unroll
            for (int half = 0; half < 2; half++) {
                const int row = bm + wm + mt * 16 + g + half * 8;
                const int col = wn + nt * 8 + t * 2;
                float2 v = { round_tf32(acc[mt][nt][half * 2 + 0]),
                             round_tf32(acc[mt][nt][half * 2 + 1]) };
                *reinterpret_cast<float2*>(&Cb[(long long)row * HDIM + col]) = v;
            }
        }
    }
}

// ===========================================================================
// Generic TF32 GEMM (proven R7 config) for fc + projections.
// B must be pre-rounded. A pre-rounded iff CVT_A==0.
// mode 1: C = round(relu(acc + bias))
// mode 2: C = Cin + 0.25*relu(acc+bias); Cr = round(C)
// mode 3: C = acc + bias;                Cr = round(C)
// ===========================================================================
template <int CVT_A>
__global__ __launch_bounds__(256, 2)
void gemm_tf32_kernel(const float* __restrict__ A, const float* __restrict__ Bm,
                      const float* __restrict__ Cin, float* __restrict__ C,
                      float* __restrict__ Cr,
                      const float* __restrict__ bias,
                      int M, int N, int K, int mode)
{
    __shared__ __align__(16) float As[2][BM * SA_STRIDE];
    __shared__ __align__(16) float Bs[2][BK * SB_STRIDE];

    const int bm = blockIdx.y * BM;

    const int tid  = threadIdx.x;
    const int lane = tid & 31;
    const int warp = tid >> 5;
    const int wm = (warp & 3) * 32;
    const int wn = (warp >> 2) * 64;
    const int g = lane >> 2;
    const int t = lane & 3;

    float acc[2][8][4];
    #pragma unroll
    for (int mt = 0; mt < 2; mt++)
        #pragma unroll
        for (int nt = 0; nt < 8; nt++)
            #pragma unroll
            for (int i = 0; i < 4; i++)
                acc[mt][nt][i] = 0.0f;

    auto load_stage = [&](int stage, int kt) {
        const float* Ag = A + (long long)bm * K + (long long)kt * BK;
        #pragma unroll
        for (int i = 0; i < 2; i++) {
            int idx = tid + i * 256;
            int r = idx >> 2;
            int c = (idx & 3) << 2;
            cp_async16(&As[stage][r * SA_STRIDE + c], Ag + (long long)r * K + c);
        }
        const float* Bg = Bm + (long long)(kt * BK) * N;
        #pragma unroll
        for (int i = 0; i < 2; i++) {
            int idx = tid + i * 256;
            int r = idx >> 5;
            int c = (idx & 31) << 2;
            cp_async16(&Bs[stage][r * SB_STRIDE + c], Bg + (long long)r * N + c);
        }
    };

    auto rd_a = [&](const float* p) -> uint32_t {
        return CVT_A ? cvt_tf32(*p) : __float_as_uint(*p);
    };

    auto compute_stage = [&](int stage) {
        #pragma unroll
        for (int ks = 0; ks < BK; ks += 8) {
            uint32_t af[2][4];
            #pragma unroll
            for (int mt = 0; mt < 2; mt++) {
                const int rb = wm + mt * 16;
                const float* as = &As[stage][0];
                af[mt][0] = rd_a(&as[(rb + g)     * SA_STRIDE + ks + t]);
                af[mt][1] = rd_a(&as[(rb + g + 8) * SA_STRIDE + ks + t]);
                af[mt][2] = rd_a(&as[(rb + g)     * SA_STRIDE + ks + t + 4]);
                af[mt][3] = rd_a(&as[(rb + g + 8) * SA_STRIDE + ks + t + 4]);
            }
            uint32_t bf[8][2];
            #pragma unroll
            for (int nt = 0; nt < 8; nt++) {
                const int nb = wn + nt * 8 + g;
                const float* bs = &Bs[stage][0];
                bf[nt][0] = __float_as_uint(bs[(ks + t)     * SB_STRIDE + nb]);
                bf[nt][1] = __float_as_uint(bs[(ks + t + 4) * SB_STRIDE + nb]);
            }
            #pragma unroll
            for (int mt = 0; mt < 2; mt++)
                #pragma unroll
                for (int nt = 0; nt < 8; nt++)
                    mma_tf32(acc[mt][nt], af[mt][0], af[mt][1], af[mt][2], af[mt][3],
                             bf[nt][0], bf[nt][1]);
        }
    };

    const int nk = K / BK;
    load_stage(0, 0);
    CP_COMMIT();
    CP_WAIT0();
    __syncthreads();

    for (int kt = 0; kt < nk; kt++) {
        const int s = kt & 1;
        if (kt + 1 < nk) {
            load_stage(s ^ 1, kt + 1);
            CP_COMMIT();
        }
        compute_stage(s);
        if (kt + 1 < nk) {
            CP_WAIT0();
            __syncthreads();
        }
    }

    #pragma unroll
    for (int mt = 0; mt < 2; mt++) {
        #pragma unroll
        for (int nt = 0; nt < 8; nt++) {
            #pragma unroll
            for (int half = 0; half < 2; half++) {
                const int row = bm + wm + mt * 16 + g + half * 8;
                const int col = wn + nt * 8 + t * 2;
                float v0 = acc[mt][nt][half * 2 + 0] + bias[col];
                float v1 = acc[mt][nt][half * 2 + 1] + bias[col + 1];
                const long long off = (long long)row * N + col;
                if (mode == 1) {
                    float2 o = { round_tf32(fmaxf(v0, 0.0f)),
                                 round_tf32(fmaxf(v1, 0.0f)) };
                    *reinterpret_cast<float2*>(&C[off]) = o;
                } else if (mode == 2) {
                    float2 hin = *reinterpret_cast<const float2*>(&Cin[off]);
                    float2 o = { hin.x + 0.25f * fmaxf(v0, 0.0f),
                                 hin.y + 0.25f * fmaxf(v1, 0.0f) };
                    *reinterpret_cast<float2*>(&C[off]) = o;
                    float2 r2 = { round_tf32(o.x), round_tf32(o.y) };
                    *reinterpret_cast<float2*>(&Cr[off]) = r2;
                } else { // mode 3
                    float2 o = { v0, v1 };
                    *reinterpret_cast<float2*>(&C[off]) = o;
                    float2 r2 = { round_tf32(v0), round_tf32(v1) };
                    *reinterpret_cast<float2*>(&Cr[off]) = r2;
                }
            }
        }
    }
}

extern "C" void kernel_launch(void* const* d_in, const int* in_sizes, int n_in,
                              void* d_out, int out_size)
{
    const float* x    = (const float*)d_in[0];
    const float* adj  = (const float*)d_in[1];
    const float* W_fc = (const float*)d_in[2];
    const float* b_fc = (const float*)d_in[3];
    const float* W1   = (const float*)d_in[4];
    const float* b1   = (const float*)d_in[5];
    const float* W2   = (const float*)d_in[6];
    const float* b2   = (const float*)d_in[7];
    float* out = (float*)d_out;

    float* base;
    cudaGetSymbolAddress((void**)&base, g_scratch);
    float* agg   = base;                     // rounded aggregation output
    float* t_hr  = base + BNH;               // rounded t / rounded h shadow
    float* wfc_r = base + W_OFF;
    float* w1_r  = wfc_r + INDIM * HDIM;
    float* w2_r  = w1_r  + HDIM * HDIM;
    float* h = out;                          // fp32 Euler state

    cudaFuncSetAttribute(agg_kernel,
                         cudaFuncAttributeMaxDynamicSharedMemorySize, AGG_SMEM_BYTES);

    // Pre-round the weight matrices.
    {
        const int thr = 256;
        int n4 = (INDIM * HDIM) / 4;
        round_copy_kernel<<<(n4 + thr - 1) / thr, thr>>>(W_fc, wfc_r, n4);
        n4 = (HDIM * HDIM) / 4;
        round_copy_kernel<<<(n4 + thr - 1) / thr, thr>>>(W1, w1_r, n4);
        round_copy_kernel<<<(n4 + thr - 1) / thr, thr>>>(W2, w2_r, n4);
    }

    dim3 blk(256);
    const dim3 agrid(1, NNODE / TBM, BATCH);

    // h = x @ W_fc + b_fc  (fp32 h + rounded shadow hr)
    gemm_tf32_kernel<1><<<dim3(1, (BATCH * NNODE) / BM, 1), blk>>>(
        x, wfc_r, nullptr, h, t_hr, b_fc,
        BATCH * NNODE, HDIM, INDIM, 3);

    for (int step = 0; step < 4; step++) {
        // agg = round(adj @ hr)
        agg_kernel<<<agrid, blk, AGG_SMEM_BYTES>>>(adj, t_hr, agg);
        // t = round(relu(agg @ W1 + b1))
        gemm_tf32_kernel<0><<<dim3(1, (BATCH * NNODE) / BM, 1), blk>>>(
            agg, w1_r, nullptr, t_hr, nullptr, b1,
            BATCH * NNODE, HDIM, HDIM, 1);
        // agg = round(adj @ t)
        agg_kernel<<<agrid, blk, AGG_SMEM_BYTES>>>(adj, t_hr, agg);
        // h += 0.25*relu(agg @ W2 + b2);  hr = round(h)
        gemm_tf32_kernel<0><<<dim3(1, (BATCH * NNODE) / BM, 1), blk>>>(
            agg, w2_r, h, h, t_hr, b2,
            BATCH * NNODE, HDIM, HDIM, 2);
    }
}

// round 13
// speedup vs baseline: 2.6264x; 1.9633x over previous
#include <cuda_runtime.h>
#include <cuda_fp16.h>
#include <cstdint>

// Problem constants
#define BATCH 32
#define NNODE 4096
#define INDIM 64
#define HDIM  128
#define BNHs ((size_t)BATCH * NNODE * HDIM)   // 16,777,216 elements

// fp16 GEMM tile config
#define BM 128
#define BN 128
#define BK 32
#define NSTAGE 4
// smem stage layout (bytes): A: 128 rows x 40 halves = 10240; B: 32 rows x 136 halves = 8704
#define SA_H 40          // A row stride in halves (32 + 8 pad) -> ldmatrix conflict-free
#define SB_H 136         // B row stride in halves (128 + 8 pad) -> ldmatrix conflict-free
#define STAGE_BYTES 18944
#define SMEM_BYTES (NSTAGE * STAGE_BYTES)   // 75776 -> 2 CTAs/SM

#define ADJ_SCALE 4096.0f
#define INV_ADJ_SCALE 0.000244140625f       // 2^-12, exact

// ---------------------------------------------------------------------------
// Single fp16 global pool (~117.5 MB):
//   [0,        BNHs)   : agg_h  (fp16 aggregation output, [b*4096+node][hid])
//   [BNHs,   2*BNHs)   : thr_h  (fp16 t / h-shadow, dual purpose; liveness disjoint)
//   [2*BNHs, 3*BNHs)   : adj_h  (fp16 adj * 4096)
//   [3*BNHs, 3.5*BNHs) : x_h    (fp16 x)
//   [3.5*BNHs, +40960) : W_fc | W1 | W2 (fp16)
// fp32 Euler state h lives in d_out.
// ---------------------------------------------------------------------------
__device__ __align__(256) __half g_h16[(BNHs * 7) / 2 + 40960];

// fp32 -> fp16 convert (with scale); n4 = count/4
__global__ void convert_half_kernel(const float* __restrict__ in, __half* __restrict__ out,
                                    int n4, float scale) {
    int i = blockIdx.x * blockDim.x + threadIdx.x;
    if (i < n4) {
        float4 v = reinterpret_cast<const float4*>(in)[i];
        __half2 p0 = __floats2half2_rn(v.x * scale, v.y * scale);
        __half2 p1 = __floats2half2_rn(v.z * scale, v.w * scale);
        uint2 u;
        u.x = *reinterpret_cast<uint32_t*>(&p0);
        u.y = *reinterpret_cast<uint32_t*>(&p1);
        reinterpret_cast<uint2*>(out)[i] = u;
    }
}

__device__ __forceinline__ void cp_async16(uint32_t smem, const void* gmem) {
    asm volatile("cp.async.cg.shared.global [%0], [%1], 16;\n" :: "r"(smem), "l"(gmem));
}
#define CP_COMMIT() asm volatile("cp.async.commit_group;\n" ::: "memory")
#define CP_WAIT0()  asm volatile("cp.async.wait_group 0;\n" ::: "memory")
#define CP_WAIT1()  asm volatile("cp.async.wait_group 1;\n" ::: "memory")
#define CP_WAIT2()  asm volatile("cp.async.wait_group 2;\n" ::: "memory")

__device__ __forceinline__ void ldsm_x4(uint32_t* r, uint32_t addr) {
    asm volatile("ldmatrix.sync.aligned.m8n8.x4.shared.b16 {%0,%1,%2,%3}, [%4];"
                 : "=r"(r[0]), "=r"(r[1]), "=r"(r[2]), "=r"(r[3]) : "r"(addr));
}
__device__ __forceinline__ void ldsm_x4_t(uint32_t* r, uint32_t addr) {
    asm volatile("ldmatrix.sync.aligned.m8n8.x4.trans.shared.b16 {%0,%1,%2,%3}, [%4];"
                 : "=r"(r[0]), "=r"(r[1]), "=r"(r[2]), "=r"(r[3]) : "r"(addr));
}
__device__ __forceinline__ void mma_fp16(float c[4], const uint32_t a[4],
                                         uint32_t b0, uint32_t b1) {
    asm volatile(
        "mma.sync.aligned.m16n8k16.row.col.f32.f16.f16.f32 "
        "{%0,%1,%2,%3}, {%4,%5,%6,%7}, {%8,%9}, {%0,%1,%2,%3};\n"
        : "+f"(c[0]), "+f"(c[1]), "+f"(c[2]), "+f"(c[3])
        : "r"(a[0]), "r"(a[1]), "r"(a[2]), "r"(a[3]), "r"(b0), "r"(b1));
}

// ===========================================================================
// Generic fp16 GEMM: acc = A[M,K] @ B[K,128], A/B fp16, fp32 accumulate.
// 4-stage cp.async pipeline, BK=32, ldmatrix fragments, 2 CTAs/SM.
// MODE 0: Ch = fp16(acc * 2^-12)                        (aggregation; z-batched B/Ch)
// MODE 1: Ch = fp16(relu(acc + bias))                   (gcn1 projection -> t)
// MODE 2: o = Cin + 0.25*relu(acc+bias); Cf = o; Ch = fp16(o)   (gcn2 + Euler)
// MODE 3: o = acc + bias; Cf = o; Ch = fp16(o)          (fc)
// ===========================================================================
template <int MODE>
__global__ __launch_bounds__(256, 2)
void hgemm_kernel(const __half* __restrict__ A, const __half* __restrict__ Bg,
                  const float* __restrict__ Cin, float* __restrict__ Cf,
                  __half* __restrict__ Ch, const float* __restrict__ bias,
                  int K, long long sBz, long long sCz, int nk)
{
    extern __shared__ __align__(16) char dsm[];
    const uint32_t sb = (uint32_t)__cvta_generic_to_shared(dsm);

    const int tid  = threadIdx.x;
    const int lane = tid & 31;
    const int warp = tid >> 5;
    const int wm = (warp & 3) * 32;   // 4 warps along M
    const int wn = (warp >> 2) * 64;  // 2 warps along N
    const int g = lane >> 2;
    const int t = lane & 3;
    const int lrow = lane & 15;
    const int lhi  = lane >> 4;

    const int bm = blockIdx.y * BM;
    const int bz = blockIdx.z;
    const __half* Ab = A + (long long)bm * K;
    const __half* Bb = Bg + (long long)bz * sBz;
    __half* Chb = Ch + (long long)bz * sCz;
    float* Cfb = Cf;               // modes 1-3 use z=0
    const float* Cinb = Cin;

    float acc[2][8][4];
    #pragma unroll
    for (int mt = 0; mt < 2; mt++)
        #pragma unroll
        for (int nt = 0; nt < 8; nt++)
            #pragma unroll
            for (int i = 0; i < 4; i++)
                acc[mt][nt][i] = 0.0f;

    auto load_stage = [&](int s, int kt) {
        const uint32_t abase = sb + s * STAGE_BYTES;
        #pragma unroll
        for (int i = 0; i < 2; i++) {          // 512 x 16B chunks for A (128 x 32 halves)
            int idx = tid + i * 256;
            int r = idx >> 2;
            int j = idx & 3;
            cp_async16(abase + r * 80 + j * 16,
                       Ab + (long long)r * K + kt * 32 + j * 8);
        }
        const uint32_t bbase = abase + 10240;
        #pragma unroll
        for (int i = 0; i < 2; i++) {          // 512 x 16B chunks for B (32 x 128 halves)
            int idx = tid + i * 256;
            int r = idx >> 4;
            int j = idx & 15;
            cp_async16(bbase + r * 272 + j * 16,
                       Bb + (long long)(kt * 32 + r) * 128 + j * 8);
        }
        CP_COMMIT();
    };

    auto compute_stage = [&](int s) {
        const uint32_t abase = sb + s * STAGE_BYTES;
        const uint32_t bbase = abase + 10240;
        #pragma unroll
        for (int ks = 0; ks < 32; ks += 16) {
            uint32_t af[2][4];
            #pragma unroll
            for (int mt = 0; mt < 2; mt++) {
                uint32_t addr = abase +
                    2u * ((wm + mt * 16 + lrow) * SA_H + ks + 8 * lhi);
                ldsm_x4(af[mt], addr);
            }
            #pragma unroll
            for (int np = 0; np < 4; np++) {
                uint32_t bf[4];
                uint32_t addr = bbase +
                    2u * ((ks + lrow) * SB_H + wn + np * 16 + 8 * lhi);
                ldsm_x4_t(bf, addr);
                #pragma unroll
                for (int mt = 0; mt < 2; mt++) {
                    mma_fp16(acc[mt][2 * np + 0], af[mt], bf[0], bf[1]);
                    mma_fp16(acc[mt][2 * np + 1], af[mt], bf[2], bf[3]);
                }
            }
        }
    };

    // Prologue: fill up to 3 stages.
    const int L = nk < 3 ? nk : 3;
    for (int s = 0; s < L; s++) load_stage(s, s);
    if (nk >= 3)      CP_WAIT2();
    else if (nk == 2) CP_WAIT1();
    else              CP_WAIT0();
    __syncthreads();

    for (int kt = 0; kt < nk; kt++) {
        compute_stage(kt & 3);
        if (kt + 1 < nk) {
            if (kt + 3 < nk) {
                load_stage((kt + 3) & 3, kt + 3);
                CP_WAIT2();
            } else {
                CP_WAIT0();
            }
            __syncthreads();
        }
    }

    // Epilogue
    #pragma unroll
    for (int mt = 0; mt < 2; mt++) {
        #pragma unroll
        for (int nt = 0; nt < 8; nt++) {
            #pragma unroll
            for (int h2 = 0; h2 < 2; h2++) {
                const int row = bm + wm + mt * 16 + g + h2 * 8;
                const int col = wn + nt * 8 + t * 2;
                float v0 = acc[mt][nt][h2 * 2 + 0];
                float v1 = acc[mt][nt][h2 * 2 + 1];
                const long long off = (long long)row * HDIM + col;
                if (MODE == 0) {
                    __half2 o = __floats2half2_rn(v0 * INV_ADJ_SCALE, v1 * INV_ADJ_SCALE);
                    *reinterpret_cast<__half2*>(&Chb[off]) = o;
                } else if (MODE == 1) {
                    v0 = fmaxf(v0 + bias[col], 0.0f);
                    v1 = fmaxf(v1 + bias[col + 1], 0.0f);
                    *reinterpret_cast<__half2*>(&Chb[off]) = __floats2half2_rn(v0, v1);
                } else if (MODE == 2) {
                    float2 hin = *reinterpret_cast<const float2*>(&Cinb[off]);
                    float2 o = { hin.x + 0.25f * fmaxf(v0 + bias[col], 0.0f),
                                 hin.y + 0.25f * fmaxf(v1 + bias[col + 1], 0.0f) };
                    *reinterpret_cast<float2*>(&Cfb[off]) = o;
                    *reinterpret_cast<__half2*>(&Chb[off]) = __floats2half2_rn(o.x, o.y);
                } else { // MODE 3
                    float2 o = { v0 + bias[col], v1 + bias[col + 1] };
                    *reinterpret_cast<float2*>(&Cfb[off]) = o;
                    *reinterpret_cast<__half2*>(&Chb[off]) = __floats2half2_rn(o.x, o.y);
                }
            }
        }
    }
}

extern "C" void kernel_launch(void* const* d_in, const int* in_sizes, int n_in,
                              void* d_out, int out_size)
{
    const float* x    = (const float*)d_in[0];
    const float* adj  = (const float*)d_in[1];
    const float* W_fc = (const float*)d_in[2];
    const float* b_fc = (const float*)d_in[3];
    const float* W1   = (const float*)d_in[4];
    const float* b1   = (const float*)d_in[5];
    const float* W2   = (const float*)d_in[6];
    const float* b2   = (const float*)d_in[7];
    float* out = (float*)d_out;

    __half* base;
    cudaGetSymbolAddress((void**)&base, g_h16);
    __half* agg_h = base;
    __half* thr_h = base + BNHs;
    __half* adj_h = base + 2 * BNHs;
    __half* x_h   = base + 3 * BNHs;
    __half* wfc_h = base + 3 * BNHs + BNHs / 2;
    __half* w1_h  = wfc_h + INDIM * HDIM;
    __half* w2_h  = w1_h + HDIM * HDIM;
    float* h = out;   // fp32 Euler state

    cudaFuncSetAttribute(hgemm_kernel<0>, cudaFuncAttributeMaxDynamicSharedMemorySize, SMEM_BYTES);
    cudaFuncSetAttribute(hgemm_kernel<1>, cudaFuncAttributeMaxDynamicSharedMemorySize, SMEM_BYTES);
    cudaFuncSetAttribute(hgemm_kernel<2>, cudaFuncAttributeMaxDynamicSharedMemorySize, SMEM_BYTES);
    cudaFuncSetAttribute(hgemm_kernel<3>, cudaFuncAttributeMaxDynamicSharedMemorySize, SMEM_BYTES);

    // fp32 -> fp16 conversions (adj pre-scaled by 4096 to avoid fp16 subnormals).
    {
        const int thr = 256;
        int n4 = (NNODE * NNODE) / 4;
        convert_half_kernel<<<(n4 + thr - 1) / thr, thr>>>(adj, adj_h, n4, ADJ_SCALE);
        n4 = (BATCH * NNODE * INDIM) / 4;
        convert_half_kernel<<<(n4 + thr - 1) / thr, thr>>>(x, x_h, n4, 1.0f);
        n4 = (INDIM * HDIM) / 4;
        convert_half_kernel<<<(n4 + thr - 1) / thr, thr>>>(W_fc, wfc_h, n4, 1.0f);
        n4 = (HDIM * HDIM) / 4;
        convert_half_kernel<<<(n4 + thr - 1) / thr, thr>>>(W1, w1_h, n4, 1.0f);
        convert_half_kernel<<<(n4 + thr - 1) / thr, thr>>>(W2, w2_h, n4, 1.0f);
    }

    dim3 blk(256);
    const long long sNH = (long long)NNODE * HDIM;
    const dim3 agrid(1, NNODE / BM, BATCH);
    const dim3 pgrid(1, (BATCH * NNODE) / BM, 1);

    // h = x @ W_fc + b_fc  (fp32 h + fp16 shadow in thr_h)
    hgemm_kernel<3><<<pgrid, blk, SMEM_BYTES>>>(
        x_h, wfc_h, nullptr, h, thr_h, b_fc, INDIM, 0, 0, INDIM / BK);

    for (int step = 0; step < 4; step++) {
        // agg = (adj_h @ h16) * 2^-12   [fp16 out]
        hgemm_kernel<0><<<agrid, blk, SMEM_BYTES>>>(
            adj_h, thr_h, nullptr, nullptr, agg_h, nullptr,
            NNODE, sNH, sNH, NNODE / BK);
        // t16 = fp16(relu(agg @ W1 + b1))
        hgemm_kernel<1><<<pgrid, blk, SMEM_BYTES>>>(
            agg_h, w1_h, nullptr, nullptr, thr_h, b1, HDIM, 0, 0, HDIM / BK);
        // agg = (adj_h @ t16) * 2^-12
        hgemm_kernel<0><<<agrid, blk, SMEM_BYTES>>>(
            adj_h, thr_h, nullptr, nullptr, agg_h, nullptr,
            NNODE, sNH, sNH, NNODE / BK);
        // h += 0.25*relu(agg @ W2 + b2);  h16 = fp16(h)
        hgemm_kernel<2><<<pgrid, blk, SMEM_BYTES>>>(
            agg_h, w2_h, h, h, thr_h, b2, HDIM, 0, 0, HDIM / BK);
    }
}

// round 14
// speedup vs baseline: 2.6993x; 1.0278x over previous
#include <cuda_runtime.h>
#include <cuda_fp16.h>
#include <cstdint>

// Problem constants
#define BATCH 32
#define NNODE 4096
#define INDIM 64
#define HDIM  128
#define BNHs ((size_t)BATCH * NNODE * HDIM)

// fp16 GEMM tile config
#define BM 128
#define BN 128
#define BK 32
#define NSTAGE 4
#define SA_H 40          // A row stride (halves) in pipeline stages
#define SB_H 136         // B/W/aggS row stride (halves)
#define STAGE_BYTES 18944
#define PIPE_BYTES (NSTAGE * STAGE_BYTES)       // 75776
#define WS_OFF PIPE_BYTES                        // W tile: 128 x 136 halves
#define FUSED_SMEM_BYTES (PIPE_BYTES + 128 * SB_H * 2)   // 110592 -> 2 CTAs/SM

#define ADJ_SCALE 4096.0f
#define INV_ADJ_SCALE 0.000244140625f            // 2^-12, exact

// ---------------------------------------------------------------------------
// fp16 global pool:
//   [0,        BNHs)   : thr_h  (fp16 t / h-shadow, dual purpose)
//   [BNHs,   2*BNHs)   : adj_h  (fp16 adj * 4096)
//   [2*BNHs, 2.5*BNHs) : x_h
//   [2.5*BNHs, +40960) : W_fc | W1 | W2 (fp16)
// fp32 Euler state h lives in d_out.
// ---------------------------------------------------------------------------
__device__ __align__(256) __half g_h16[(BNHs * 5) / 2 + 40960];

__global__ void convert_half_kernel(const float* __restrict__ in, __half* __restrict__ out,
                                    int n4, float scale) {
    int i = blockIdx.x * blockDim.x + threadIdx.x;
    if (i < n4) {
        float4 v = reinterpret_cast<const float4*>(in)[i];
        __half2 p0 = __floats2half2_rn(v.x * scale, v.y * scale);
        __half2 p1 = __floats2half2_rn(v.z * scale, v.w * scale);
        uint2 u;
        u.x = *reinterpret_cast<uint32_t*>(&p0);
        u.y = *reinterpret_cast<uint32_t*>(&p1);
        reinterpret_cast<uint2*>(out)[i] = u;
    }
}

__device__ __forceinline__ void cp_async16(uint32_t smem, const void* gmem) {
    asm volatile("cp.async.cg.shared.global [%0], [%1], 16;\n" :: "r"(smem), "l"(gmem));
}
#define CP_COMMIT() asm volatile("cp.async.commit_group;\n" ::: "memory")
#define CP_WAIT0()  asm volatile("cp.async.wait_group 0;\n" ::: "memory")
#define CP_WAIT2()  asm volatile("cp.async.wait_group 2;\n" ::: "memory")

__device__ __forceinline__ void ldsm_x4(uint32_t* r, uint32_t addr) {
    asm volatile("ldmatrix.sync.aligned.m8n8.x4.shared.b16 {%0,%1,%2,%3}, [%4];"
                 : "=r"(r[0]), "=r"(r[1]), "=r"(r[2]), "=r"(r[3]) : "r"(addr));
}
__device__ __forceinline__ void ldsm_x4_t(uint32_t* r, uint32_t addr) {
    asm volatile("ldmatrix.sync.aligned.m8n8.x4.trans.shared.b16 {%0,%1,%2,%3}, [%4];"
                 : "=r"(r[0]), "=r"(r[1]), "=r"(r[2]), "=r"(r[3]) : "r"(addr));
}
__device__ __forceinline__ void mma_fp16(float c[4], const uint32_t a[4],
                                         uint32_t b0, uint32_t b1) {
    asm volatile(
        "mma.sync.aligned.m16n8k16.row.col.f32.f16.f16.f32 "
        "{%0,%1,%2,%3}, {%4,%5,%6,%7}, {%8,%9}, {%0,%1,%2,%3};\n"
        : "+f"(c[0]), "+f"(c[1]), "+f"(c[2]), "+f"(c[3])
        : "r"(a[0]), "r"(a[1]), "r"(a[2]), "r"(a[3]), "r"(b0), "r"(b1));
}

// ===========================================================================
// Fused GCN layer: per CTA (128 nodes x 128 hidden, batch z):
//   agg  = (adj_h[rows,:] @ Hsrc16[z]) * 2^-12       (K=4096 fp16 mainloop)
//   proj = agg16 @ W                                 (K=128, on-chip)
//   EULER==0: thr_out = fp16(relu(proj + bias))
//   EULER==1: hn = h + 0.25*relu(proj + bias); h = hn; thr_out = fp16(hn)
// ===========================================================================
template <int EULER>
__global__ __launch_bounds__(256, 2)
void gcn_fused_kernel(const __half* __restrict__ A, const __half* __restrict__ Hsrc,
                      const __half* __restrict__ Wr, const float* __restrict__ bias,
                      __half* __restrict__ ChOut, float* __restrict__ hGlob)
{
    extern __shared__ __align__(16) char dsm[];
    const uint32_t sb = (uint32_t)__cvta_generic_to_shared(dsm);

    const int tid  = threadIdx.x;
    const int lane = tid & 31;
    const int warp = tid >> 5;
    const int wm = (warp & 3) * 32;   // 4 warps along M
    const int wn = (warp >> 2) * 64;  // 2 warps along N
    const int g = lane >> 2;
    const int t = lane & 3;
    const int lrow = lane & 15;
    const int lhi  = lane >> 4;

    const int bm = blockIdx.y * BM;
    const int bz = blockIdx.z;
    const long long sNH = (long long)NNODE * HDIM;
    const __half* Ab = A + (long long)bm * NNODE;
    const __half* Bb = Hsrc + (long long)bz * sNH;
    __half* Chb = ChOut + (long long)bz * sNH + (long long)bm * HDIM;
    float* hb = EULER ? (hGlob + (long long)bz * sNH + (long long)bm * HDIM) : nullptr;

    float acc[2][8][4];
    #pragma unroll
    for (int mt = 0; mt < 2; mt++)
        #pragma unroll
        for (int nt = 0; nt < 8; nt++)
            #pragma unroll
            for (int i = 0; i < 4; i++)
                acc[mt][nt][i] = 0.0f;

    auto load_stage = [&](int s, int kt) {
        const uint32_t abase = sb + s * STAGE_BYTES;
        #pragma unroll
        for (int i = 0; i < 2; i++) {
            int idx = tid + i * 256;
            int r = idx >> 2;
            int j = idx & 3;
            cp_async16(abase + r * 80 + j * 16,
                       Ab + (long long)r * NNODE + kt * 32 + j * 8);
        }
        const uint32_t bbase = abase + 10240;
        #pragma unroll
        for (int i = 0; i < 2; i++) {
            int idx = tid + i * 256;
            int r = idx >> 4;
            int j = idx & 15;
            cp_async16(bbase + r * 272 + j * 16,
                       Bb + (long long)(kt * 32 + r) * 128 + j * 8);
        }
        CP_COMMIT();
    };

    auto compute_stage = [&](int s) {
        const uint32_t abase = sb + s * STAGE_BYTES;
        const uint32_t bbase = abase + 10240;
        #pragma unroll
        for (int ks = 0; ks < 32; ks += 16) {
            uint32_t af[2][4];
            #pragma unroll
            for (int mt = 0; mt < 2; mt++) {
                uint32_t addr = abase +
                    2u * ((wm + mt * 16 + lrow) * SA_H + ks + 8 * lhi);
                ldsm_x4(af[mt], addr);
            }
            #pragma unroll
            for (int np = 0; np < 4; np++) {
                uint32_t bf[4];
                uint32_t addr = bbase +
                    2u * ((ks + lrow) * SB_H + wn + np * 16 + 8 * lhi);
                ldsm_x4_t(bf, addr);
                #pragma unroll
                for (int mt = 0; mt < 2; mt++) {
                    mma_fp16(acc[mt][2 * np + 0], af[mt], bf[0], bf[1]);
                    mma_fp16(acc[mt][2 * np + 1], af[mt], bf[2], bf[3]);
                }
            }
        }
    };

    // Prologue: W tile joins stage 0's commit group (so group accounting is
    // unchanged: wait_group 2 => group0 (W + stage0) complete).
    {
        const uint32_t wbase = sb + WS_OFF;
        #pragma unroll
        for (int i = 0; i < 8; i++) {            // 128 rows x 16 chunks = 2048
            int idx = tid + i * 256;
            int r = idx >> 4;
            int j = idx & 15;
            cp_async16(wbase + r * 272 + j * 16, Wr + r * 128 + j * 8);
        }
    }
    load_stage(0, 0);      // commits W + stage0 together
    load_stage(1, 1);
    load_stage(2, 2);
    CP_WAIT2();
    __syncthreads();

    const int nk = NNODE / BK;   // 128
    for (int kt = 0; kt < nk; kt++) {
        compute_stage(kt & 3);
        if (kt + 1 < nk) {
            if (kt + 3 < nk) {
                load_stage((kt + 3) & 3, kt + 3);
                CP_WAIT2();
            } else {
                CP_WAIT0();
            }
            __syncthreads();
        }
    }

    // ---- stage fp16(agg * 2^-12) into smem (dead pipeline region) ----
    __syncthreads();
    #pragma unroll
    for (int mt = 0; mt < 2; mt++) {
        #pragma unroll
        for (int nt = 0; nt < 8; nt++) {
            #pragma unroll
            for (int h2 = 0; h2 < 2; h2++) {
                const int row = wm + mt * 16 + g + h2 * 8;
                const int col = wn + nt * 8 + t * 2;
                __half2 v = __floats2half2_rn(acc[mt][nt][h2 * 2 + 0] * INV_ADJ_SCALE,
                                              acc[mt][nt][h2 * 2 + 1] * INV_ADJ_SCALE);
                *reinterpret_cast<__half2*>(dsm + row * (SB_H * 2) + col * 2) = v;
            }
        }
    }
    __syncthreads();

    // ---- on-chip projection: acc = aggS @ W  (K = 128) ----
    #pragma unroll
    for (int mt = 0; mt < 2; mt++)
        #pragma unroll
        for (int nt = 0; nt < 8; nt++)
            #pragma unroll
            for (int i = 0; i < 4; i++)
                acc[mt][nt][i] = 0.0f;

    #pragma unroll
    for (int ks = 0; ks < HDIM; ks += 16) {
        uint32_t af[2][4];
        #pragma unroll
        for (int mt = 0; mt < 2; mt++) {
            uint32_t addr = sb + 2u * ((wm + mt * 16 + lrow) * SB_H + ks + 8 * lhi);
            ldsm_x4(af[mt], addr);
        }
        #pragma unroll
        for (int np = 0; np < 4; np++) {
            uint32_t bf[4];
            uint32_t addr = sb + WS_OFF +
                2u * ((ks + lrow) * SB_H + wn + np * 16 + 8 * lhi);
            ldsm_x4_t(bf, addr);
            #pragma unroll
            for (int mt = 0; mt < 2; mt++) {
                mma_fp16(acc[mt][2 * np + 0], af[mt], bf[0], bf[1]);
                mma_fp16(acc[mt][2 * np + 1], af[mt], bf[2], bf[3]);
            }
        }
    }

    // ---- final epilogue ----
    #pragma unroll
    for (int mt = 0; mt < 2; mt++) {
        #pragma unroll
        for (int nt = 0; nt < 8; nt++) {
            #pragma unroll
            for (int h2 = 0; h2 < 2; h2++) {
                const int row = wm + mt * 16 + g + h2 * 8;
                const int col = wn + nt * 8 + t * 2;
                float v0 = acc[mt][nt][h2 * 2 + 0] + bias[col];
                float v1 = acc[mt][nt][h2 * 2 + 1] + bias[col + 1];
                const long long off = (long long)row * HDIM + col;
                if (EULER == 0) {
                    v0 = fmaxf(v0, 0.0f);
                    v1 = fmaxf(v1, 0.0f);
                    *reinterpret_cast<__half2*>(&Chb[off]) = __floats2half2_rn(v0, v1);
                } else {
                    float2 hin = *reinterpret_cast<const float2*>(&hb[off]);
                    float2 o = { hin.x + 0.25f * fmaxf(v0, 0.0f),
                                 hin.y + 0.25f * fmaxf(v1, 0.0f) };
                    *reinterpret_cast<float2*>(&hb[off]) = o;
                    *reinterpret_cast<__half2*>(&Chb[off]) = __floats2half2_rn(o.x, o.y);
                }
            }
        }
    }
}

// ===========================================================================
// fc kernel: h = x @ W_fc + b_fc (fp32 out + fp16 shadow). K = 64, 2 stages.
// ===========================================================================
__global__ __launch_bounds__(256, 2)
void fc_kernel(const __half* __restrict__ A, const __half* __restrict__ Bg,
               float* __restrict__ Cf, __half* __restrict__ Ch,
               const float* __restrict__ bias)
{
    extern __shared__ __align__(16) char dsm[];
    const uint32_t sb = (uint32_t)__cvta_generic_to_shared(dsm);
    const int K = INDIM;

    const int tid  = threadIdx.x;
    const int lane = tid & 31;
    const int warp = tid >> 5;
    const int wm = (warp & 3) * 32;
    const int wn = (warp >> 2) * 64;
    const int g = lane >> 2;
    const int t = lane & 3;
    const int lrow = lane & 15;
    const int lhi  = lane >> 4;

    const int bm = blockIdx.y * BM;
    const __half* Ab = A + (long long)bm * K;

    float acc[2][8][4];
    #pragma unroll
    for (int mt = 0; mt < 2; mt++)
        #pragma unroll
        for (int nt = 0; nt < 8; nt++)
            #pragma unroll
            for (int i = 0; i < 4; i++)
                acc[mt][nt][i] = 0.0f;

    auto load_stage = [&](int s, int kt) {
        const uint32_t abase = sb + s * STAGE_BYTES;
        #pragma unroll
        for (int i = 0; i < 2; i++) {
            int idx = tid + i * 256;
            int r = idx >> 2;
            int j = idx & 3;
            cp_async16(abase + r * 80 + j * 16,
                       Ab + (long long)r * K + kt * 32 + j * 8);
        }
        const uint32_t bbase = abase + 10240;
        #pragma unroll
        for (int i = 0; i < 2; i++) {
            int idx = tid + i * 256;
            int r = idx >> 4;
            int j = idx & 15;
            cp_async16(bbase + r * 272 + j * 16,
                       Bg + (long long)(kt * 32 + r) * 128 + j * 8);
        }
        CP_COMMIT();
    };

    auto compute_stage = [&](int s) {
        const uint32_t abase = sb + s * STAGE_BYTES;
        const uint32_t bbase = abase + 10240;
        #pragma unroll
        for (int ks = 0; ks < 32; ks += 16) {
            uint32_t af[2][4];
            #pragma unroll
            for (int mt = 0; mt < 2; mt++) {
                uint32_t addr = abase +
                    2u * ((wm + mt * 16 + lrow) * SA_H + ks + 8 * lhi);
                ldsm_x4(af[mt], addr);
            }
            #pragma unroll
            for (int np = 0; np < 4; np++) {
                uint32_t bf[4];
                uint32_t addr = bbase +
                    2u * ((ks + lrow) * SB_H + wn + np * 16 + 8 * lhi);
                ldsm_x4_t(bf, addr);
                #pragma unroll
                for (int mt = 0; mt < 2; mt++) {
                    mma_fp16(acc[mt][2 * np + 0], af[mt], bf[0], bf[1]);
                    mma_fp16(acc[mt][2 * np + 1], af[mt], bf[2], bf[3]);
                }
            }
        }
    };

    load_stage(0, 0);
    load_stage(1, 1);
    CP_WAIT0();
    __syncthreads();
    compute_stage(0);
    compute_stage(1);

    #pragma unroll
    for (int mt = 0; mt < 2; mt++) {
        #pragma unroll
        for (int nt = 0; nt < 8; nt++) {
            #pragma unroll
            for (int h2 = 0; h2 < 2; h2++) {
                const int row = bm + wm + mt * 16 + g + h2 * 8;
                const int col = wn + nt * 8 + t * 2;
                float2 o = { acc[mt][nt][h2 * 2 + 0] + bias[col],
                             acc[mt][nt][h2 * 2 + 1] + bias[col + 1] };
                const long long off = (long long)row * HDIM + col;
                *reinterpret_cast<float2*>(&Cf[off]) = o;
                *reinterpret_cast<__half2*>(&Ch[off]) = __floats2half2_rn(o.x, o.y);
            }
        }
    }
}

extern "C" void kernel_launch(void* const* d_in, const int* in_sizes, int n_in,
                              void* d_out, int out_size)
{
    const float* x    = (const float*)d_in[0];
    const float* adj  = (const float*)d_in[1];
    const float* W_fc = (const float*)d_in[2];
    const float* b_fc = (const float*)d_in[3];
    const float* W1   = (const float*)d_in[4];
    const float* b1   = (const float*)d_in[5];
    const float* W2   = (const float*)d_in[6];
    const float* b2   = (const float*)d_in[7];
    float* out = (float*)d_out;

    __half* base;
    cudaGetSymbolAddress((void**)&base, g_h16);
    __half* thr_h = base;                      // t16 / h16 shadow
    __half* adj_h = base + BNHs;
    __half* x_h   = base + 2 * BNHs;
    __half* wfc_h = base + 2 * BNHs + BNHs / 2;
    __half* w1_h  = wfc_h + INDIM * HDIM;
    __half* w2_h  = w1_h + HDIM * HDIM;
    float* h = out;    // fp32 Euler state

    cudaFuncSetAttribute(gcn_fused_kernel<0>, cudaFuncAttributeMaxDynamicSharedMemorySize, FUSED_SMEM_BYTES);
    cudaFuncSetAttribute(gcn_fused_kernel<1>, cudaFuncAttributeMaxDynamicSharedMemorySize, FUSED_SMEM_BYTES);
    cudaFuncSetAttribute(fc_kernel, cudaFuncAttributeMaxDynamicSharedMemorySize, 2 * STAGE_BYTES);

    // fp32 -> fp16 conversions (adj pre-scaled by 4096).
    {
        const int thr = 256;
        int n4 = (NNODE * NNODE) / 4;
        convert_half_kernel<<<(n4 + thr - 1) / thr, thr>>>(adj, adj_h, n4, ADJ_SCALE);
        n4 = (BATCH * NNODE * INDIM) / 4;
        convert_half_kernel<<<(n4 + thr - 1) / thr, thr>>>(x, x_h, n4, 1.0f);
        n4 = (INDIM * HDIM) / 4;
        convert_half_kernel<<<(n4 + thr - 1) / thr, thr>>>(W_fc, wfc_h, n4, 1.0f);
        n4 = (HDIM * HDIM) / 4;
        convert_half_kernel<<<(n4 + thr - 1) / thr, thr>>>(W1, w1_h, n4, 1.0f);
        convert_half_kernel<<<(n4 + thr - 1) / thr, thr>>>(W2, w2_h, n4, 1.0f);
    }

    dim3 blk(256);
    const dim3 fgrid(1, NNODE / BM, BATCH);

    // h = x @ W_fc + b_fc
    fc_kernel<<<dim3(1, (BATCH * NNODE) / BM, 1), blk, 2 * STAGE_BYTES>>>(
        x_h, wfc_h, h, thr_h, b_fc);

    for (int step = 0; step < 4; step++) {
        // t16 = fp16(relu((adj @ h16) @ W1 + b1))
        gcn_fused_kernel<0><<<fgrid, blk, FUSED_SMEM_BYTES>>>(
            adj_h, thr_h, w1_h, b1, thr_h, nullptr);
        // h += 0.25*relu((adj @ t16) @ W2 + b2);  h16 = fp16(h)
        gcn_fused_kernel<1><<<fgrid, blk, FUSED_SMEM_BYTES>>>(
            adj_h, thr_h, w2_h, b2, thr_h, h);
    }
}